// round 2
// baseline (speedup 1.0000x reference)
#include <cuda_runtime.h>
#include <cuda_bf16.h>
#include <math.h>

// Problem constants (shapes are fixed by the dataset).
#define DIM   256
#define MAXN  100000
#define MAXE  800000
#define SCANB 1024          // elements per scan block
#define MAXBLK 128          // >= ceil(MAXN/SCANB) = 98

// -------- device-global scratch (allocation-free workaround) --------
__device__ float g_support[MAXN * DIM];   // x @ W
__device__ int   g_counts[MAXN];          // per-row edge counts / scan input
__device__ int   g_scan[MAXN];            // per-block inclusive scan
__device__ int   g_rowptr[MAXN + 1];      // CSR row pointers
__device__ int   g_cursor[MAXN];          // atomic fill cursors
__device__ int   g_bsum[MAXBLK];          // scan block sums
__device__ int   g_esrc[MAXE];            // CSR-ordered src node ids
__device__ float g_eval[MAXE];            // CSR-ordered edge values (adj+adj_w)

// ---------------- CSR construction ----------------
__global__ void k_zero_counts(int n) {
    int i = blockIdx.x * blockDim.x + threadIdx.x;
    if (i < n) g_counts[i] = 0;
}

__global__ void k_hist(const int* __restrict__ dst, int E) {
    int e = blockIdx.x * blockDim.x + threadIdx.x;
    if (e < E) atomicAdd(&g_counts[dst[e]], 1);
}

// Per-block inclusive scan (Hillis-Steele), 1024 threads / 1024 elems.
__global__ void k_scan_block(int n) {
    __shared__ int s[SCANB];
    int t = threadIdx.x;
    int gid = blockIdx.x * SCANB + t;
    int v = (gid < n) ? g_counts[gid] : 0;
    s[t] = v;
    __syncthreads();
    #pragma unroll
    for (int off = 1; off < SCANB; off <<= 1) {
        int x = (t >= off) ? s[t - off] : 0;
        __syncthreads();
        s[t] += x;
        __syncthreads();
    }
    if (gid < n) g_scan[gid] = s[t];
    if (t == SCANB - 1) g_bsum[blockIdx.x] = s[t];
}

__global__ void k_scan_sums(int nb) {
    if (threadIdx.x == 0 && blockIdx.x == 0) {
        int acc = 0;
        for (int i = 0; i < nb; i++) { int v = g_bsum[i]; g_bsum[i] = acc; acc += v; }
    }
}

__global__ void k_finalize_rowptr(int n) {
    int i = blockIdx.x * blockDim.x + threadIdx.x;
    if (i < n) g_rowptr[i + 1] = g_scan[i] + g_bsum[i >> 10];
    if (i == 0) g_rowptr[0] = 0;
}

__global__ void k_cursor_init(int n) {
    int i = blockIdx.x * blockDim.x + threadIdx.x;
    if (i < n) g_cursor[i] = g_rowptr[i];
}

__global__ void k_fill(const int* __restrict__ dst, const int* __restrict__ src,
                       const float* __restrict__ av, const float* __restrict__ aw, int E) {
    int e = blockIdx.x * blockDim.x + threadIdx.x;
    if (e < E) {
        int d = dst[e];
        int p = atomicAdd(&g_cursor[d], 1);
        g_esrc[p] = src[e];
        g_eval[p] = av[e] + aw[e];
    }
}

// ---------------- GEMM: support = x @ W ----------------
// 128x128 block tile, BK=16, 256 threads, 8x8 per-thread microtile.
__global__ __launch_bounds__(256) void k_gemm(const float* __restrict__ X,
                                              const float* __restrict__ W, int Nrows) {
    const int BM = 128, BN = 128, BK = 16;
    __shared__ float As[BK][BM];
    __shared__ float Bs[BK][BN];

    int block_m = blockIdx.x * BM;
    int block_n = blockIdx.y * BN;
    int tid = threadIdx.x;
    int tr = tid >> 4;       // 0..15 (row micro group)
    int tc = tid & 15;       // 0..15 (col micro group)

    float acc[8][8];
    #pragma unroll
    for (int i = 0; i < 8; i++)
        #pragma unroll
        for (int j = 0; j < 8; j++) acc[i][j] = 0.0f;

    for (int k0 = 0; k0 < DIM; k0 += BK) {
        // Load A tile: 128 rows x 16 k = 512 float4s
        #pragma unroll
        for (int l = 0; l < 2; l++) {
            int f = tid + l * 256;            // 0..511
            int arow = f >> 2;                // 4 float4 per row
            int ak4  = f & 3;
            int grow = block_m + arow;
            float4 a = make_float4(0.f, 0.f, 0.f, 0.f);
            if (grow < Nrows)
                a = *reinterpret_cast<const float4*>(&X[(size_t)grow * DIM + k0 + ak4 * 4]);
            As[ak4 * 4 + 0][arow] = a.x;
            As[ak4 * 4 + 1][arow] = a.y;
            As[ak4 * 4 + 2][arow] = a.z;
            As[ak4 * 4 + 3][arow] = a.w;
        }
        // Load B tile: 16 rows x 128 cols = 512 float4s
        #pragma unroll
        for (int l = 0; l < 2; l++) {
            int f = tid + l * 256;
            int brow = f >> 5;                // 32 float4 per row
            int bc4  = f & 31;
            float4 b = *reinterpret_cast<const float4*>(&W[(size_t)(k0 + brow) * DIM + block_n + bc4 * 4]);
            *reinterpret_cast<float4*>(&Bs[brow][bc4 * 4]) = b;
        }
        __syncthreads();

        #pragma unroll
        for (int kk = 0; kk < BK; kk++) {
            float4 a0 = *reinterpret_cast<const float4*>(&As[kk][tr * 8]);
            float4 a1 = *reinterpret_cast<const float4*>(&As[kk][tr * 8 + 4]);
            float4 b0 = *reinterpret_cast<const float4*>(&Bs[kk][tc * 8]);
            float4 b1 = *reinterpret_cast<const float4*>(&Bs[kk][tc * 8 + 4]);
            float a[8] = {a0.x, a0.y, a0.z, a0.w, a1.x, a1.y, a1.z, a1.w};
            float b[8] = {b0.x, b0.y, b0.z, b0.w, b1.x, b1.y, b1.z, b1.w};
            #pragma unroll
            for (int i = 0; i < 8; i++)
                #pragma unroll
                for (int j = 0; j < 8; j++)
                    acc[i][j] = fmaf(a[i], b[j], acc[i][j]);
        }
        __syncthreads();
    }

    // Store 8x8 microtile
    #pragma unroll
    for (int i = 0; i < 8; i++) {
        int grow = block_m + tr * 8 + i;
        if (grow < Nrows) {
            float4 v0 = make_float4(acc[i][0], acc[i][1], acc[i][2], acc[i][3]);
            float4 v1 = make_float4(acc[i][4], acc[i][5], acc[i][6], acc[i][7]);
            *reinterpret_cast<float4*>(&g_support[(size_t)grow * DIM + block_n + tc * 8])     = v0;
            *reinterpret_cast<float4*>(&g_support[(size_t)grow * DIM + block_n + tc * 8 + 4]) = v1;
        }
    }
}

// ---------------- SpMM + fused L2 normalize ----------------
// One block per output row; thread t owns dimension t.
__global__ __launch_bounds__(DIM) void k_spmm_norm(float* __restrict__ out, int n) {
    int row = blockIdx.x;
    if (row >= n) return;
    int t = threadIdx.x;

    int beg = g_rowptr[row];
    int end = g_rowptr[row + 1];

    float acc = 0.0f;
    for (int e = beg; e < end; e++) {
        int   s = g_esrc[e];                  // broadcast load
        float v = g_eval[e];                  // broadcast load
        acc = fmaf(v, g_support[(size_t)s * DIM + t], acc);  // coalesced gather
    }

    __shared__ float red[DIM];
    red[t] = acc * acc;
    __syncthreads();
    #pragma unroll
    for (int s = DIM / 2; s >= 32; s >>= 1) {
        if (t < s) red[t] += red[t + s];
        __syncthreads();
    }
    float ss = red[0];
    if (t < 32) {
        float w = red[t];
        #pragma unroll
        for (int o = 16; o > 0; o >>= 1) w += __shfl_down_sync(0xFFFFFFFF, w, o);
        if (t == 0) red[0] = w;
    }
    __syncthreads();
    ss = red[0];

    float norm  = sqrtf(ss);
    float denom = fmaxf(norm, 1e-12f);
    out[(size_t)row * DIM + t] = acc / denom;
}

// ---------------- launch ----------------
extern "C" void kernel_launch(void* const* d_in, const int* in_sizes, int n_in,
                              void* d_out, int out_size) {
    const float* x  = (const float*)d_in[0];   // [N, 256]
    const float* W  = (const float*)d_in[1];   // [256, 256]
    const float* av = (const float*)d_in[2];   // [E]
    const float* aw = (const float*)d_in[3];   // [E]
    const int*   ei = (const int*)  d_in[4];   // [2, E] row-major: dst then src
    float* out = (float*)d_out;

    int N = in_sizes[0] / DIM;
    int E = in_sizes[2];
    const int* dst = ei;
    const int* src = ei + E;

    int nb = (N + SCANB - 1) / SCANB;

    // GEMM (independent of CSR build)
    dim3 ggrid((N + 127) / 128, DIM / 128);
    k_gemm<<<ggrid, 256>>>(x, W, N);

    // CSR build
    k_zero_counts<<<(N + 255) / 256, 256>>>(N);
    k_hist<<<(E + 255) / 256, 256>>>(dst, E);
    k_scan_block<<<nb, SCANB>>>(N);
    k_scan_sums<<<1, 32>>>(nb);
    k_finalize_rowptr<<<(N + 255) / 256, 256>>>(N);
    k_cursor_init<<<(N + 255) / 256, 256>>>(N);
    k_fill<<<(E + 255) / 256, 256>>>(dst, src, av, aw, E);

    // Aggregate + normalize
    k_spmm_norm<<<N, DIM>>>(out, N);
}

// round 5
// speedup vs baseline: 1.1300x; 1.1300x over previous
#include <cuda_runtime.h>
#include <cuda_bf16.h>
#include <math.h>
#include <stdint.h>

// Problem constants (shapes are fixed by the dataset).
#define DIM   256
#define MAXN  100000
#define MAXE  800000
#define SCANB 1024          // elements per scan block
#define MAXBLK 128          // >= ceil(MAXN/SCANB) = 98

// -------- device-global scratch (allocation-free workaround) --------
__device__ float g_support[MAXN * DIM];   // x @ W
__device__ int   g_counts[MAXN];
__device__ int   g_scan[MAXN];
__device__ int   g_rowptr[MAXN + 1];
__device__ int   g_cursor[MAXN];
__device__ int   g_bsum[MAXBLK];
__device__ int   g_esrc[MAXE];
__device__ float g_eval[MAXE];

// ---------------- CSR construction ----------------
__global__ void k_zero_counts(int n) {
    int i = blockIdx.x * blockDim.x + threadIdx.x;
    if (i < n) g_counts[i] = 0;
}

__global__ void k_hist(const int* __restrict__ dst, int E) {
    int e = blockIdx.x * blockDim.x + threadIdx.x;
    if (e < E) atomicAdd(&g_counts[dst[e]], 1);
}

__global__ void k_scan_block(int n) {
    __shared__ int s[SCANB];
    int t = threadIdx.x;
    int gid = blockIdx.x * SCANB + t;
    int v = (gid < n) ? g_counts[gid] : 0;
    s[t] = v;
    __syncthreads();
    #pragma unroll
    for (int off = 1; off < SCANB; off <<= 1) {
        int x = (t >= off) ? s[t - off] : 0;
        __syncthreads();
        s[t] += x;
        __syncthreads();
    }
    if (gid < n) g_scan[gid] = s[t];
    if (t == SCANB - 1) g_bsum[blockIdx.x] = s[t];
}

__global__ void k_scan_sums(int nb) {
    if (threadIdx.x == 0 && blockIdx.x == 0) {
        int acc = 0;
        for (int i = 0; i < nb; i++) { int v = g_bsum[i]; g_bsum[i] = acc; acc += v; }
    }
}

__global__ void k_finalize_rowptr(int n) {
    int i = blockIdx.x * blockDim.x + threadIdx.x;
    if (i < n) g_rowptr[i + 1] = g_scan[i] + g_bsum[i >> 10];
    if (i == 0) g_rowptr[0] = 0;
}

__global__ void k_cursor_init(int n) {
    int i = blockIdx.x * blockDim.x + threadIdx.x;
    if (i < n) g_cursor[i] = g_rowptr[i];
}

__global__ void k_fill(const int* __restrict__ dst, const int* __restrict__ src,
                       const float* __restrict__ av, const float* __restrict__ aw, int E) {
    int e = blockIdx.x * blockDim.x + threadIdx.x;
    if (e < E) {
        int d = dst[e];
        int p = atomicAdd(&g_cursor[d], 1);
        g_esrc[p] = src[e];
        g_eval[p] = av[e] + aw[e];
    }
}

// ---------------- GEMM: support = x @ W  (3xTF32 tensor-core) ----------------
// 128x128 block tile, BK=16, 256 threads = 8 warps in 2(M) x 4(N).
// Warp tile 64x32 = 4x4 m16n8k8 sub-tiles. hi/lo tf32 split for fp32 accuracy.

// cvt to tf32 requires a .b32 destination (tf32 is an opaque 32-bit format).
__device__ __forceinline__ uint32_t tf32_rna(float x) {
    uint32_t r;
    asm("cvt.rna.tf32.f32 %0, %1;" : "=r"(r) : "f"(x));
    return r;
}

__device__ __forceinline__ void mma_tf32(float c[4], uint32_t a0, uint32_t a1,
                                         uint32_t a2, uint32_t a3,
                                         uint32_t b0, uint32_t b1) {
    asm volatile(
        "mma.sync.aligned.m16n8k8.row.col.f32.tf32.tf32.f32 "
        "{%0,%1,%2,%3}, {%4,%5,%6,%7}, {%8,%9}, {%0,%1,%2,%3};"
        : "+f"(c[0]), "+f"(c[1]), "+f"(c[2]), "+f"(c[3])
        : "r"(a0), "r"(a1), "r"(a2), "r"(a3), "r"(b0), "r"(b1));
}

#define GBM 128
#define GBN 128
#define GBK 16
#define A_STRIDE 20    // ≡ 4 (mod 32): conflict-free fragment loads
#define B_STRIDE 136   // ≡ 8 (mod 32): conflict-free fragment loads

__global__ __launch_bounds__(256) void k_gemm_tf32(const float* __restrict__ X,
                                                   const float* __restrict__ W, int Nrows) {
    __shared__ uint32_t Ah[GBM][A_STRIDE];
    __shared__ uint32_t Al[GBM][A_STRIDE];
    __shared__ uint32_t Bh[GBK][B_STRIDE];
    __shared__ uint32_t Bl[GBK][B_STRIDE];

    const int tid  = threadIdx.x;
    const int lane = tid & 31;
    const int wid  = tid >> 5;
    const int warp_m = wid >> 2;        // 0..1
    const int warp_n = wid & 3;         // 0..3
    const int block_m = blockIdx.x * GBM;
    const int block_n = blockIdx.y * GBN;
    const int g  = lane >> 2;           // groupID 0..7
    const int tg = lane & 3;            // thread-in-group 0..3

    float acc[4][4][4];
    #pragma unroll
    for (int i = 0; i < 4; i++)
        #pragma unroll
        for (int j = 0; j < 4; j++)
            #pragma unroll
            for (int r = 0; r < 4; r++) acc[i][j][r] = 0.0f;

    for (int k0 = 0; k0 < DIM; k0 += GBK) {
        // Load A tile: 128 rows x 16 k = 512 float4, 2 per thread
        #pragma unroll
        for (int l = 0; l < 2; l++) {
            int idx  = tid + l * 256;       // 0..511
            int arow = idx >> 2;            // 4 float4 per row
            int ac4  = idx & 3;
            int grow = block_m + arow;
            float4 a = make_float4(0.f, 0.f, 0.f, 0.f);
            if (grow < Nrows)
                a = *reinterpret_cast<const float4*>(&X[(size_t)grow * DIM + k0 + ac4 * 4]);
            float av4[4] = {a.x, a.y, a.z, a.w};
            #pragma unroll
            for (int c = 0; c < 4; c++) {
                uint32_t h = tf32_rna(av4[c]);
                Ah[arow][ac4 * 4 + c] = h;
                Al[arow][ac4 * 4 + c] = tf32_rna(av4[c] - __uint_as_float(h));
            }
        }
        // Load B tile: 16 k x 128 n = 512 float4, 2 per thread
        #pragma unroll
        for (int l = 0; l < 2; l++) {
            int idx  = tid + l * 256;
            int brow = idx >> 5;            // 32 float4 per row
            int bc4  = idx & 31;
            float4 b = *reinterpret_cast<const float4*>(&W[(size_t)(k0 + brow) * DIM + block_n + bc4 * 4]);
            float bv4[4] = {b.x, b.y, b.z, b.w};
            #pragma unroll
            for (int c = 0; c < 4; c++) {
                uint32_t h = tf32_rna(bv4[c]);
                Bh[brow][bc4 * 4 + c] = h;
                Bl[brow][bc4 * 4 + c] = tf32_rna(bv4[c] - __uint_as_float(h));
            }
        }
        __syncthreads();

        #pragma unroll
        for (int kk = 0; kk < GBK; kk += 8) {
            // A fragments (hi+lo) for 4 M sub-tiles
            uint32_t fah[4][4], fal[4][4];
            #pragma unroll
            for (int mt = 0; mt < 4; mt++) {
                int m = warp_m * 64 + mt * 16 + g;
                int k = kk + tg;
                fah[mt][0] = Ah[m][k];
                fah[mt][1] = Ah[m + 8][k];
                fah[mt][2] = Ah[m][k + 4];
                fah[mt][3] = Ah[m + 8][k + 4];
                fal[mt][0] = Al[m][k];
                fal[mt][1] = Al[m + 8][k];
                fal[mt][2] = Al[m][k + 4];
                fal[mt][3] = Al[m + 8][k + 4];
            }
            // B fragments (hi+lo) for 4 N sub-tiles
            uint32_t fbh[4][2], fbl[4][2];
            #pragma unroll
            for (int nt = 0; nt < 4; nt++) {
                int n = warp_n * 32 + nt * 8 + g;
                int k = kk + tg;
                fbh[nt][0] = Bh[k][n];
                fbh[nt][1] = Bh[k + 4][n];
                fbl[nt][0] = Bl[k][n];
                fbl[nt][1] = Bl[k + 4][n];
            }
            #pragma unroll
            for (int mt = 0; mt < 4; mt++)
                #pragma unroll
                for (int nt = 0; nt < 4; nt++) {
                    mma_tf32(acc[mt][nt], fal[mt][0], fal[mt][1], fal[mt][2], fal[mt][3],
                             fbh[nt][0], fbh[nt][1]);
                    mma_tf32(acc[mt][nt], fah[mt][0], fah[mt][1], fah[mt][2], fah[mt][3],
                             fbl[nt][0], fbl[nt][1]);
                    mma_tf32(acc[mt][nt], fah[mt][0], fah[mt][1], fah[mt][2], fah[mt][3],
                             fbh[nt][0], fbh[nt][1]);
                }
        }
        __syncthreads();
    }

    // Epilogue: write 64x32 warp tile
    #pragma unroll
    for (int mt = 0; mt < 4; mt++) {
        int r0 = block_m + warp_m * 64 + mt * 16 + g;
        #pragma unroll
        for (int nt = 0; nt < 4; nt++) {
            int c = block_n + warp_n * 32 + nt * 8 + 2 * tg;
            if (r0 < Nrows)
                *reinterpret_cast<float2*>(&g_support[(size_t)r0 * DIM + c]) =
                    make_float2(acc[mt][nt][0], acc[mt][nt][1]);
            if (r0 + 8 < Nrows)
                *reinterpret_cast<float2*>(&g_support[(size_t)(r0 + 8) * DIM + c]) =
                    make_float2(acc[mt][nt][2], acc[mt][nt][3]);
        }
    }
}

// ---------------- SpMM + fused L2 normalize ----------------
__global__ __launch_bounds__(DIM) void k_spmm_norm(float* __restrict__ out, int n) {
    const int row = blockIdx.x;
    if (row >= n) return;
    const int t = threadIdx.x;

    const int beg = g_rowptr[row];
    const int end = g_rowptr[row + 1];

    float acc0 = 0.0f, acc1 = 0.0f;
    int e = beg;
    for (; e + 1 < end; e += 2) {
        int   s0 = __ldg(&g_esrc[e]);
        int   s1 = __ldg(&g_esrc[e + 1]);
        float v0 = __ldg(&g_eval[e]);
        float v1 = __ldg(&g_eval[e + 1]);
        acc0 = fmaf(v0, g_support[(size_t)s0 * DIM + t], acc0);
        acc1 = fmaf(v1, g_support[(size_t)s1 * DIM + t], acc1);
    }
    if (e < end) {
        int   s0 = __ldg(&g_esrc[e]);
        float v0 = __ldg(&g_eval[e]);
        acc0 = fmaf(v0, g_support[(size_t)s0 * DIM + t], acc0);
    }
    float acc = acc0 + acc1;

    __shared__ float red[DIM];
    red[t] = acc * acc;
    __syncthreads();
    #pragma unroll
    for (int s = DIM / 2; s >= 32; s >>= 1) {
        if (t < s) red[t] += red[t + s];
        __syncthreads();
    }
    if (t < 32) {
        float w = red[t];
        #pragma unroll
        for (int o = 16; o > 0; o >>= 1) w += __shfl_down_sync(0xFFFFFFFF, w, o);
        if (t == 0) red[0] = w;
    }
    __syncthreads();
    float ss = red[0];

    float norm  = sqrtf(ss);
    float denom = fmaxf(norm, 1e-12f);
    out[(size_t)row * DIM + t] = acc / denom;
}

// ---------------- launch ----------------
extern "C" void kernel_launch(void* const* d_in, const int* in_sizes, int n_in,
                              void* d_out, int out_size) {
    const float* x  = (const float*)d_in[0];   // [N, 256]
    const float* W  = (const float*)d_in[1];   // [256, 256]
    const float* av = (const float*)d_in[2];   // [E]
    const float* aw = (const float*)d_in[3];   // [E]
    const int*   ei = (const int*)  d_in[4];   // [2, E]: dst row, then src row
    float* out = (float*)d_out;

    int N = in_sizes[0] / DIM;
    int E = in_sizes[2];
    const int* dst = ei;
    const int* src = ei + E;

    int nb = (N + SCANB - 1) / SCANB;

    // GEMM (independent of CSR build)
    dim3 ggrid((N + GBM - 1) / GBM, DIM / GBN);
    k_gemm_tf32<<<ggrid, 256>>>(x, W, N);

    // CSR build
    k_zero_counts<<<(N + 255) / 256, 256>>>(N);
    k_hist<<<(E + 255) / 256, 256>>>(dst, E);
    k_scan_block<<<nb, SCANB>>>(N);
    k_scan_sums<<<1, 32>>>(nb);
    k_finalize_rowptr<<<(N + 255) / 256, 256>>>(N);
    k_cursor_init<<<(N + 255) / 256, 256>>>(N);
    k_fill<<<(E + 255) / 256, 256>>>(dst, src, av, aw, E);

    // Aggregate + normalize
    k_spmm_norm<<<N, DIM>>>(out, N);
}

// round 7
// speedup vs baseline: 1.4085x; 1.2464x over previous
#include <cuda_runtime.h>
#include <cuda_bf16.h>
#include <math.h>
#include <stdint.h>

// Problem constants (shapes are fixed by the dataset).
#define DIM   256
#define MAXN  100000
#define MAXE  800000
#define SCANB 1024
#define MAXBLK 128          // >= ceil(MAXN/SCANB) = 98

// -------- device-global scratch (allocation-free workaround) --------
__device__ float g_support[MAXN * DIM];   // x @ W
__device__ int   g_counts[MAXN];
__device__ int   g_scan[MAXN];
__device__ int   g_rowptr[MAXN + 1];
__device__ int   g_cursor[MAXN];
__device__ int   g_bsum[MAXBLK];
__device__ int   g_esrc[MAXE];
__device__ float g_eval[MAXE];

// ---------------- CSR construction ----------------
__global__ void k_zero_counts(int n) {
    int i = blockIdx.x * blockDim.x + threadIdx.x;
    if (i < n) g_counts[i] = 0;
}

__global__ void k_hist(const int* __restrict__ dst, int E) {
    int e = blockIdx.x * blockDim.x + threadIdx.x;
    if (e < E) atomicAdd(&g_counts[dst[e]], 1);
}

__global__ void k_scan_block(int n) {
    __shared__ int s[SCANB];
    int t = threadIdx.x;
    int gid = blockIdx.x * SCANB + t;
    int v = (gid < n) ? g_counts[gid] : 0;
    s[t] = v;
    __syncthreads();
    #pragma unroll
    for (int off = 1; off < SCANB; off <<= 1) {
        int x = (t >= off) ? s[t - off] : 0;
        __syncthreads();
        s[t] += x;
        __syncthreads();
    }
    if (gid < n) g_scan[gid] = s[t];
    if (t == SCANB - 1) g_bsum[blockIdx.x] = s[t];
}

// Parallel exclusive scan over the (<=128) block sums.
__global__ void k_scan_sums(int nb) {
    __shared__ int s[MAXBLK];
    int t = threadIdx.x;                 // 128 threads
    int v = (t < nb) ? g_bsum[t] : 0;
    s[t] = v;
    __syncthreads();
    #pragma unroll
    for (int off = 1; off < MAXBLK; off <<= 1) {
        int x = (t >= off) ? s[t - off] : 0;
        __syncthreads();
        s[t] += x;
        __syncthreads();
    }
    if (t < nb) g_bsum[t] = s[t] - v;    // exclusive
}

// rowptr[i+1] and cursor[i] in one pass (cursor_init folded in).
__global__ void k_finalize_rowptr(int n) {
    int i = blockIdx.x * blockDim.x + threadIdx.x;
    if (i < n) {
        g_rowptr[i + 1] = g_scan[i] + g_bsum[i >> 10];
        int rp0 = (i == 0) ? 0 : (g_scan[i - 1] + g_bsum[(i - 1) >> 10]);
        g_cursor[i] = rp0;
        if (i == 0) g_rowptr[0] = 0;
    }
}

__global__ void k_fill(const int* __restrict__ dst, const int* __restrict__ src,
                       const float* __restrict__ av, const float* __restrict__ aw, int E) {
    int e = blockIdx.x * blockDim.x + threadIdx.x;
    if (e < E) {
        int d = dst[e];
        int p = atomicAdd(&g_cursor[d], 1);
        g_esrc[p] = src[e];
        g_eval[p] = av[e] + aw[e];
    }
}

// ---------------- GEMM: support = x @ W  (3xBF16 tensor-core) ----------------
// 128x128 block tile, BK=32, 256 threads = 8 warps in 2(M) x 4(N).
// Warp tile 64x32 = 4x4 m16n8k16 sub-tiles, bf16 hi/lo split (error ~2^-17).

__device__ __forceinline__ uint32_t pack_bf16(float a, float b) {
    __nv_bfloat162 h = __floats2bfloat162_rn(a, b);
    return *reinterpret_cast<uint32_t*>(&h);
}
__device__ __forceinline__ float bf16_hi_f(float a) {
    return __bfloat162float(__float2bfloat16_rn(a));
}

__device__ __forceinline__ void mma_bf16(float c[4], uint32_t a0, uint32_t a1,
                                         uint32_t a2, uint32_t a3,
                                         uint32_t b0, uint32_t b1) {
    asm volatile(
        "mma.sync.aligned.m16n8k16.row.col.f32.bf16.bf16.f32 "
        "{%0,%1,%2,%3}, {%4,%5,%6,%7}, {%8,%9}, {%0,%1,%2,%3};"
        : "+f"(c[0]), "+f"(c[1]), "+f"(c[2]), "+f"(c[3])
        : "r"(a0), "r"(a1), "r"(a2), "r"(a3), "r"(b0), "r"(b1));
}

#define GBM 128
#define GBN 128
#define GBK 32
#define KP  (GBK / 2)      // 16 k-pairs
#define A_PITCH 20         // u32 pitch ≡ 4 (mod 32): conflict-free A frag loads
#define B_PITCH 136        // u32 pitch ≡ 8 (mod 32): conflict-free B frag loads

__global__ __launch_bounds__(256) void k_gemm_bf16(const float* __restrict__ X,
                                                   const float* __restrict__ W, int Nrows) {
    // Packed bf16x2 (pairs along k).
    __shared__ uint32_t Ash[GBM][A_PITCH];
    __shared__ uint32_t Asl[GBM][A_PITCH];
    __shared__ uint32_t Bsh[KP][B_PITCH];
    __shared__ uint32_t Bsl[KP][B_PITCH];

    const int tid  = threadIdx.x;
    const int lane = tid & 31;
    const int wid  = tid >> 5;
    const int warp_m = wid >> 2;        // 0..1
    const int warp_n = wid & 3;         // 0..3
    const int block_m = blockIdx.x * GBM;
    const int block_n = blockIdx.y * GBN;
    const int g  = lane >> 2;           // 0..7
    const int tg = lane & 3;            // 0..3

    float acc[4][4][4];
    #pragma unroll
    for (int i = 0; i < 4; i++)
        #pragma unroll
        for (int j = 0; j < 4; j++)
            #pragma unroll
            for (int r = 0; r < 4; r++) acc[i][j][r] = 0.0f;

    for (int k0 = 0; k0 < DIM; k0 += GBK) {
        // ---- Load A tile: 128 rows x 32 k = 1024 float4, 4 per thread ----
        #pragma unroll
        for (int l = 0; l < 4; l++) {
            int idx = tid + l * 256;        // 0..1023
            int r   = idx >> 3;             // 8 float4 per row
            int k4  = idx & 7;
            int grow = block_m + r;
            float4 a = make_float4(0.f, 0.f, 0.f, 0.f);
            if (grow < Nrows)
                a = *reinterpret_cast<const float4*>(&X[(size_t)grow * DIM + k0 + k4 * 4]);
            float hx = bf16_hi_f(a.x), hy = bf16_hi_f(a.y), hz = bf16_hi_f(a.z), hw = bf16_hi_f(a.w);
            Ash[r][2 * k4 + 0] = pack_bf16(hx, hy);
            Ash[r][2 * k4 + 1] = pack_bf16(hz, hw);
            Asl[r][2 * k4 + 0] = pack_bf16(a.x - hx, a.y - hy);
            Asl[r][2 * k4 + 1] = pack_bf16(a.z - hz, a.w - hw);
        }
        // ---- Load B tile: 32 k x 128 n, transposed into k-pair layout ----
        #pragma unroll
        for (int l = 0; l < 2; l++) {
            int idx = tid + l * 256;        // 0..511
            int kp  = idx >> 5;             // 0..15
            int n4  = idx & 31;
            float4 w0 = *reinterpret_cast<const float4*>(&W[(size_t)(k0 + 2 * kp)     * DIM + block_n + n4 * 4]);
            float4 w1 = *reinterpret_cast<const float4*>(&W[(size_t)(k0 + 2 * kp + 1) * DIM + block_n + n4 * 4]);
            float a0[4] = {w0.x, w0.y, w0.z, w0.w};
            float a1[4] = {w1.x, w1.y, w1.z, w1.w};
            #pragma unroll
            for (int j = 0; j < 4; j++) {
                float h0 = bf16_hi_f(a0[j]);
                float h1 = bf16_hi_f(a1[j]);
                Bsh[kp][n4 * 4 + j] = pack_bf16(h0, h1);
                Bsl[kp][n4 * 4 + j] = pack_bf16(a0[j] - h0, a1[j] - h1);
            }
        }
        __syncthreads();

        #pragma unroll
        for (int kc = 0; kc < KP; kc += 8) {   // two k16 chunks per BK=32
            uint32_t fah[4][4], fal[4][4];
            #pragma unroll
            for (int mt = 0; mt < 4; mt++) {
                int m = warp_m * 64 + mt * 16 + g;
                fah[mt][0] = Ash[m][kc + tg];
                fah[mt][1] = Ash[m + 8][kc + tg];
                fah[mt][2] = Ash[m][kc + tg + 4];
                fah[mt][3] = Ash[m + 8][kc + tg + 4];
                fal[mt][0] = Asl[m][kc + tg];
                fal[mt][1] = Asl[m + 8][kc + tg];
                fal[mt][2] = Asl[m][kc + tg + 4];
                fal[mt][3] = Asl[m + 8][kc + tg + 4];
            }
            uint32_t fbh[4][2], fbl[4][2];
            #pragma unroll
            for (int nt = 0; nt < 4; nt++) {
                int n = warp_n * 32 + nt * 8 + g;
                fbh[nt][0] = Bsh[kc + tg][n];
                fbh[nt][1] = Bsh[kc + tg + 4][n];
                fbl[nt][0] = Bsl[kc + tg][n];
                fbl[nt][1] = Bsl[kc + tg + 4][n];
            }
            #pragma unroll
            for (int mt = 0; mt < 4; mt++)
                #pragma unroll
                for (int nt = 0; nt < 4; nt++) {
                    mma_bf16(acc[mt][nt], fal[mt][0], fal[mt][1], fal[mt][2], fal[mt][3],
                             fbh[nt][0], fbh[nt][1]);
                    mma_bf16(acc[mt][nt], fah[mt][0], fah[mt][1], fah[mt][2], fah[mt][3],
                             fbl[nt][0], fbl[nt][1]);
                    mma_bf16(acc[mt][nt], fah[mt][0], fah[mt][1], fah[mt][2], fah[mt][3],
                             fbh[nt][0], fbh[nt][1]);
                }
        }
        __syncthreads();
    }

    // Epilogue: write 64x32 warp tile
    #pragma unroll
    for (int mt = 0; mt < 4; mt++) {
        int r0 = block_m + warp_m * 64 + mt * 16 + g;
        #pragma unroll
        for (int nt = 0; nt < 4; nt++) {
            int c = block_n + warp_n * 32 + nt * 8 + 2 * tg;
            if (r0 < Nrows)
                *reinterpret_cast<float2*>(&g_support[(size_t)r0 * DIM + c]) =
                    make_float2(acc[mt][nt][0], acc[mt][nt][1]);
            if (r0 + 8 < Nrows)
                *reinterpret_cast<float2*>(&g_support[(size_t)(r0 + 8) * DIM + c]) =
                    make_float2(acc[mt][nt][2], acc[mt][nt][3]);
        }
    }
}

// ---------------- SpMM + fused L2 normalize ----------------
__global__ __launch_bounds__(DIM) void k_spmm_norm(float* __restrict__ out, int n) {
    const int row = blockIdx.x;
    if (row >= n) return;
    const int t = threadIdx.x;

    const int beg = g_rowptr[row];
    const int end = g_rowptr[row + 1];

    float acc0 = 0.0f, acc1 = 0.0f;
    int e = beg;
    for (; e + 1 < end; e += 2) {
        int   s0 = __ldg(&g_esrc[e]);
        int   s1 = __ldg(&g_esrc[e + 1]);
        float v0 = __ldg(&g_eval[e]);
        float v1 = __ldg(&g_eval[e + 1]);
        acc0 = fmaf(v0, g_support[(size_t)s0 * DIM + t], acc0);
        acc1 = fmaf(v1, g_support[(size_t)s1 * DIM + t], acc1);
    }
    if (e < end) {
        int   s0 = __ldg(&g_esrc[e]);
        float v0 = __ldg(&g_eval[e]);
        acc0 = fmaf(v0, g_support[(size_t)s0 * DIM + t], acc0);
    }
    float acc = acc0 + acc1;

    __shared__ float red[DIM];
    red[t] = acc * acc;
    __syncthreads();
    #pragma unroll
    for (int s = DIM / 2; s >= 32; s >>= 1) {
        if (t < s) red[t] += red[t + s];
        __syncthreads();
    }
    if (t < 32) {
        float w = red[t];
        #pragma unroll
        for (int o = 16; o > 0; o >>= 1) w += __shfl_down_sync(0xFFFFFFFF, w, o);
        if (t == 0) red[0] = w;
    }
    __syncthreads();
    float ss = red[0];

    float norm  = sqrtf(ss);
    float denom = fmaxf(norm, 1e-12f);
    out[(size_t)row * DIM + t] = acc / denom;
}

// ---------------- launch ----------------
extern "C" void kernel_launch(void* const* d_in, const int* in_sizes, int n_in,
                              void* d_out, int out_size) {
    const float* x  = (const float*)d_in[0];   // [N, 256]
    const float* W  = (const float*)d_in[1];   // [256, 256]
    const float* av = (const float*)d_in[2];   // [E]
    const float* aw = (const float*)d_in[3];   // [E]
    const int*   ei = (const int*)  d_in[4];   // [2, E]: dst row, then src row
    float* out = (float*)d_out;

    int N = in_sizes[0] / DIM;
    int E = in_sizes[2];
    const int* dst = ei;
    const int* src = ei + E;

    int nb = (N + SCANB - 1) / SCANB;

    // GEMM (independent of CSR build)
    dim3 ggrid((N + GBM - 1) / GBM, DIM / GBN);
    k_gemm_bf16<<<ggrid, 256>>>(x, W, N);

    // CSR build
    k_zero_counts<<<(N + 255) / 256, 256>>>(N);
    k_hist<<<(E + 255) / 256, 256>>>(dst, E);
    k_scan_block<<<nb, SCANB>>>(N);
    k_scan_sums<<<1, MAXBLK>>>(nb);
    k_finalize_rowptr<<<(N + 255) / 256, 256>>>(N);
    k_fill<<<(E + 255) / 256, 256>>>(dst, src, av, aw, E);

    // Aggregate + normalize
    k_spmm_norm<<<N, DIM>>>(out, N);
}